// round 14
// baseline (speedup 1.0000x reference)
#include <cuda_runtime.h>
#include <cuda_fp16.h>
#include <cstdint>
#include <cstddef>

#define NB 128
#define NS 512
#define ND 128
#define NH 1024
#define NO 64
#define NIN 257
#define KP2 272       // fp16-padded input size (17 x k16)
#define NG 4096

// ---------------- device scratch ----------------
__device__ __align__(16) __half d_xt16[NS * NB * KP2];
__device__ __align__(16) __half d_wih16[NG * KP2];
__device__ __align__(16) __half d_whh16[NG * NH];
__device__ __align__(16) float d_bias[NG];
__device__ __align__(16) __half d_xg16[(size_t)NS * NB * NG];  // fp16 input-gate precompute
__device__ __align__(1024) __half d_h16[2][NB * NH];   // permuted+swizzled layout
__device__ __align__(16) int d_pflag[128 * 8];         // producer step flags (stride 8)

// ---------------- helpers ----------------
__device__ __forceinline__ unsigned smem_u32(const void* p) {
    return (unsigned)__cvta_generic_to_shared(p);
}
__device__ __forceinline__ void cpa16(unsigned s, const void* g) {
    asm volatile("cp.async.cg.shared.global [%0], [%1], 16;\n" :: "r"(s), "l"(g));
}
__device__ __forceinline__ void cp_commit() { asm volatile("cp.async.commit_group;\n"); }
__device__ __forceinline__ void cp_wait0() { asm volatile("cp.async.wait_group 0;\n" ::: "memory"); }

#define CP_WAITN(n) asm volatile("cp.async.wait_group " #n ";\n" ::: "memory")

__device__ __forceinline__ float sigf(float x) { return 1.f / (1.f + __expf(-x)); }
__device__ __forceinline__ float tanhf_(float x) {
    float e = __expf(-2.f * fabsf(x));
    float t = (1.f - e) / (1.f + e);
    return copysignf(t, x);
}

// fp16 HMMA m16n8k16, fp32 accum
__device__ __forceinline__ void mma16(float* c, const unsigned* a, const unsigned* b) {
    asm volatile(
        "mma.sync.aligned.m16n8k16.row.col.f32.f16.f16.f32 "
        "{%0,%1,%2,%3}, {%4,%5,%6,%7}, {%8,%9}, {%0,%1,%2,%3};\n"
        : "+f"(c[0]), "+f"(c[1]), "+f"(c[2]), "+f"(c[3])
        : "r"(a[0]), "r"(a[1]), "r"(a[2]), "r"(a[3]), "r"(b[0]), "r"(b[1]));
}

// ---------------- prep kernels ----------------
__global__ void k_prep_xt(const float* __restrict__ x, const float* __restrict__ mask,
                          const float* __restrict__ ti) {
    int idx = blockIdx.x * 256 + threadIdx.x;
    if (idx >= NS * NB * KP2) return;
    int r = idx / KP2, k = idx - r * KP2;
    int s = r >> 7, b = r & 127;
    float v = 0.f;
    if (k < ND)            v = x[(b * NS + s) * ND + k];
    else if (k < 2 * ND)   v = mask[(b * NS + s) * ND + (k - ND)];
    else if (k == 2 * ND)  v = ti[b * NS + s];
    d_xt16[idx] = __float2half_rn(v);
}

__global__ void k_prep_w(const float* __restrict__ wih, const float* __restrict__ whh,
                         const float* __restrict__ bih, const float* __restrict__ bhh) {
    int idx = blockIdx.x * 256 + threadIdx.x;
    if (idx < NG * KP2) {
        int g = idx / KP2, k = idx - g * KP2;
        float v = (k < NIN) ? wih[g * NIN + k] : 0.f;
        d_wih16[idx] = __float2half_rn(v);
    }
    if (idx < NG * NH) d_whh16[idx] = __float2half_rn(whh[idx]);
    if (idx < NG) d_bias[idx] = bih[idx] + bhh[idx];
    if (idx < 1024) d_pflag[idx] = 0;                          // reset flags each launch
    if (idx < 16384) ((uint4*)&d_h16[0][0])[idx] = make_uint4(0, 0, 0, 0);  // h0 = 0
}

// ---------------- XG GEMM (fp16 HMMA m16n8k16, unchanged from R12) ----------------
#define X_STRIDE 280
#define XG_SMEM ((64 + 128) * X_STRIDE * 2)    /* 107520 B */

__global__ void __launch_bounds__(256, 2) k_xg() {
    extern __shared__ __half smh[];
    __half* Wsm = smh;                         // [64][280]
    __half* Asm = smh + 64 * X_STRIDE;         // [128][280]
    const int tid = threadIdx.x;
    const int n0 = blockIdx.x * 64;
    const int row0 = blockIdx.y * NB;

    unsigned wb = smem_u32(Wsm);
    unsigned ab = smem_u32(Asm);

    for (int q = tid; q < 64 * 34; q += 256) {
        int r = q / 34, c = q - r * 34;
        cpa16(wb + (unsigned)(r * X_STRIDE * 2 + c * 16), d_wih16 + (n0 + r) * KP2 + c * 8);
    }
    for (int q = tid; q < 128 * 34; q += 256) {
        int r = q / 34, c = q - r * 34;
        cpa16(ab + (unsigned)(r * X_STRIDE * 2 + c * 16), d_xt16 + (row0 + r) * KP2 + c * 8);
    }
    cp_commit();
    cp_wait0();
    __syncthreads();

    const int wid = tid >> 5, l = tid & 31;
    const int wm = wid >> 1, wn = wid & 1;
    const int lr = l >> 2, lc = l & 3;

    float acc[2][4][4];
#pragma unroll
    for (int i = 0; i < 2; i++)
#pragma unroll
        for (int j = 0; j < 4; j++)
#pragma unroll
            for (int k = 0; k < 4; k++) acc[i][j][k] = 0.f;

    for (int tb = 0; tb < 17; tb++) {
        const int kb = tb * 16 + 2 * lc;
        unsigned afr[2][4];
#pragma unroll
        for (int mt = 0; mt < 2; mt++) {
            const __half* p = Asm + (wm * 32 + mt * 16 + lr) * X_STRIDE + kb;
            afr[mt][0] = *(const unsigned*)(p);
            afr[mt][1] = *(const unsigned*)(p + 8 * X_STRIDE);
            afr[mt][2] = *(const unsigned*)(p + 8);
            afr[mt][3] = *(const unsigned*)(p + 8 * X_STRIDE + 8);
        }
#pragma unroll
        for (int nt = 0; nt < 4; nt++) {
            const __half* p = Wsm + (wn * 32 + nt * 8 + lr) * X_STRIDE + kb;
            unsigned bfr[2] = { *(const unsigned*)(p), *(const unsigned*)(p + 8) };
#pragma unroll
            for (int mt = 0; mt < 2; mt++) mma16(acc[mt][nt], afr[mt], bfr);
        }
    }

#pragma unroll
    for (int mt = 0; mt < 2; mt++) {
#pragma unroll
        for (int nt = 0; nt < 4; nt++) {
            int g = n0 + wn * 32 + nt * 8 + 2 * lc;
            float2 bias = *(const float2*)(d_bias + g);
#pragma unroll
            for (int p = 0; p < 2; p++) {
                int row = row0 + wm * 32 + mt * 16 + lr + p * 8;
                float ox = acc[mt][nt][2 * p + 0] + bias.x;
                float oy = acc[mt][nt][2 * p + 1] + bias.y;
                *(__half2*)(d_xg16 + (size_t)row * NG + g) = __floats2half2_rn(ox, oy);
            }
        }
    }
}

// ---------------- persistent recurrent kernel: full-K warps, register cell ----------------
// 128 CTAs (1/SM). CTA cid owns hidden units [8*cid, 8*cid+8) = 32 gate cols (N=32).
// 8 warps = 8 m-slices of 16 batch rows. Warp: M=16, N=32, K=1024 (64 k16 iters).
// No cross-warp reduction: HMMA accum layout gives thread (lr,lc) the full i/f/g/o
// for rows {lr,lr+8} x units {2lc,2lc+1} in registers; cell state lives there too.
// Per-warp A ring: 16 slots x 512 B, prefetch depth 8, 1 cp.async chunk/lane/iter.
// ONE __syncthreads per step (before flag publish).
#define R_W_OFF   0                      /* 65536 B: W slice (64 tb x 512 halves) */
#define R_A_OFF   65536                  /* 65536 B: 8 warps x 16 slots x 512 B   */
#define R_SMEM    131072

__global__ void __launch_bounds__(256, 1) k_rec() {
    extern __shared__ char smraw[];
    __half* Wsm = (__half*)(smraw + R_W_OFF);
    __half* Aring = (__half*)(smraw + R_A_OFF);

    const int tid = threadIdx.x;
    const int w = tid >> 5, lane = tid & 31;
    const int cid = blockIdx.x;
    const int J0 = cid * 8;
    const int lr = lane >> 2, lc = lane & 3;

    __half* Aw = Aring + w * (16 * 256);           // 16 slots x 256 halves
    const unsigned awbase = smem_u32(Aw);

    // ---- W slice -> Wsm (permuted + swizzled; same layout as R12) ----
    for (int q = tid; q < 32768; q += 256) {
        int n = q >> 10, k = q & 1023;
        int g = n >> 3, u = n & 7;
        __half v = d_whh16[(size_t)(g * 1024 + J0 + u) * NH + k];
        int tb = k >> 4, j = (k >> 1) & 7;
        int p = j & 3, hs = j >> 2;
        int slot = p ^ (n & 3);
        Wsm[tb * 512 + n * 16 + slot * 4 + hs * 2 + (k & 1)] = v;
    }
    __syncthreads();

    // cell state in registers: thread owns rows m=w*16+lr(+8), units j=2lc,2lc+1
    float creg[2][2] = {{0.f, 0.f}, {0.f, 0.f}};

    const int f_row = lane >> 1, f_half = lane & 1;    // cp.async chunk map (1/lane/iter)
    const int sl = (lc ^ (lr & 3)) * 4;

    for (int s = 0; s < NS; s++) {
        const __half* hr = &d_h16[s & 1][0];
        __half* hw = &d_h16[(s + 1) & 1][0];
        const __half* xgS = d_xg16 + (size_t)s * NB * NG;

        // prefetch xg for this thread's 2x2 items (independent of flags)
        float2 xgr[2][4];
#pragma unroll
        for (int q = 0; q < 2; q++) {
            int m = w * 16 + lr + q * 8;
            const __half* xp = xgS + (size_t)m * NG + J0 + 2 * lc;
#pragma unroll
            for (int g = 0; g < 4; g++)
                xgr[q][g] = __half22float2(__ldg((const __half2*)(xp + g * 1024)));
        }

        // ---- bulk acquire-poll: all 128 producers at step >= s (4 flags/lane) ----
        {
            const int* f0 = d_pflag + lane * 8;
            int v0, v1, v2, v3;
            do {
                asm volatile("ld.acquire.gpu.global.b32 %0, [%1];" : "=r"(v0) : "l"(f0) : "memory");
                asm volatile("ld.acquire.gpu.global.b32 %0, [%1];" : "=r"(v1) : "l"(f0 + 256) : "memory");
                asm volatile("ld.acquire.gpu.global.b32 %0, [%1];" : "=r"(v2) : "l"(f0 + 512) : "memory");
                asm volatile("ld.acquire.gpu.global.b32 %0, [%1];" : "=r"(v3) : "l"(f0 + 768) : "memory");
            } while (__any_sync(0xFFFFFFFFu, (v0 < s) | (v1 < s) | (v2 < s) | (v3 < s)));
        }

        float acc[4][4];
#pragma unroll
        for (int a = 0; a < 4; a++)
#pragma unroll
            for (int c = 0; c < 4; c++) acc[a][c] = 0.f;

        // source row for this lane's cp.async chunk
        const __half* hrow = hr + (size_t)(w * 16 + f_row) * NH + f_half * 8;
        const unsigned dstb = awbase + (unsigned)(f_row * 32 + f_half * 16);

        // prologue: blocks 0..7 into slots 0..7
#pragma unroll
        for (int pb = 0; pb < 8; pb++) {
            cpa16(dstb + pb * 512, hrow + pb * 16);
            cp_commit();
        }

#define R_COMPUTE(T)                                                             \
        {                                                                        \
            const __half* Ab = Aw + ((T) & 15) * 256;                            \
            uint2 lo = *(const uint2*)(Ab + lr * 16 + sl);                       \
            uint2 hi = *(const uint2*)(Ab + (lr + 8) * 16 + sl);                 \
            unsigned afr[4] = { lo.x, hi.x, lo.y, hi.y };                        \
            const __half* Bt = Wsm + (T) * 512;                                  \
            _Pragma("unroll")                                                    \
            for (int nt = 0; nt < 4; nt++) {                                     \
                uint2 bv = *(const uint2*)(Bt + (nt * 8 + lr) * 16 + sl);        \
                unsigned bfr[2] = { bv.x, bv.y };                                \
                mma16(acc[nt], afr, bfr);                                        \
            }                                                                    \
        }

#pragma unroll 4
        for (int t = 0; t < 56; t++) {
            cpa16(dstb + ((t + 8) & 15) * 512, hrow + (t + 8) * 16);
            cp_commit();
            CP_WAITN(8);
            __syncwarp();
            R_COMPUTE(t);
        }
        // tail: drain remaining groups with decreasing waits
#pragma unroll
        for (int i = 0; i < 8; i++) {
            if (i == 0) { CP_WAITN(7); } else if (i == 1) { CP_WAITN(6); }
            else if (i == 2) { CP_WAITN(5); } else if (i == 3) { CP_WAITN(4); }
            else if (i == 4) { CP_WAITN(3); } else if (i == 5) { CP_WAITN(2); }
            else if (i == 6) { CP_WAITN(1); } else { CP_WAITN(0); }
            __syncwarp();
            R_COMPUTE(56 + i);
        }

        // ---- register epilogue: gates + cell + permuted/swizzled h store ----
#pragma unroll
        for (int q = 0; q < 2; q++) {
            int m = w * 16 + lr + q * 8;
            float h0, h1;
            {
                float iv = sigf(acc[0][2 * q] + xgr[q][0].x);
                float fv = sigf(acc[1][2 * q] + xgr[q][1].x);
                float gv = tanhf_(acc[2][2 * q] + xgr[q][2].x);
                float ov = sigf(acc[3][2 * q] + xgr[q][3].x);
                creg[q][0] = fv * creg[q][0] + iv * gv;
                h0 = ov * tanhf_(creg[q][0]);
            }
            {
                float iv = sigf(acc[0][2 * q + 1] + xgr[q][0].y);
                float fv = sigf(acc[1][2 * q + 1] + xgr[q][1].y);
                float gv = tanhf_(acc[2][2 * q + 1] + xgr[q][2].y);
                float ov = sigf(acc[3][2 * q + 1] + xgr[q][3].y);
                creg[q][1] = fv * creg[q][1] + iv * gv;
                h1 = ov * tanhf_(creg[q][1]);
            }
            int slotg = lc ^ (m & 3);
            char* dst = (char*)hw + (size_t)m * 2048 + (cid >> 1) * 32 + slotg * 8 + (cid & 1) * 4;
            *(__half2*)dst = __floats2half2_rn(h0, h1);
        }

        // publish: h stores -> release fence -> barrier -> release flag
        asm volatile("fence.acq_rel.gpu;" ::: "memory");
        __syncthreads();
        if (tid == 0)
            asm volatile("st.release.gpu.global.b32 [%0], %1;"
                         :: "l"(d_pflag + cid * 8), "r"(s + 1) : "memory");
    }
}

// ---------------- final FC: out = h_last @ W_fc.T + b_fc (un-permute) ----------------
__global__ void k_fc(const float* __restrict__ wfc, const float* __restrict__ bfc,
                     float* __restrict__ out) {
    int idx = blockIdx.x * 256 + threadIdx.x;
    if (idx >= NB * NO) return;
    int b = idx >> 6, o = idx & 63;
    const __half* hrow = &d_h16[0][0] + (size_t)b * NH;   // NS even -> final h in buffer 0
    const float* wrow = wfc + o * NH;
    float sacc = 0.f;
#pragma unroll 4
    for (int k = 0; k < NH; k++) {
        int j = (k >> 1) & 7;
        int p = j & 3, hs = j >> 2;
        int hi = (k >> 4) * 16 + (p ^ (b & 3)) * 4 + hs * 2 + (k & 1);
        sacc += __half2float(hrow[hi]) * __ldg(wrow + k);
    }
    out[idx] = sacc + bfc[o];
}

// ---------------- launch ----------------
extern "C" void kernel_launch(void* const* d_in, const int* in_sizes, int n_in,
                              void* d_out, int out_size) {
    const float* x    = (const float*)d_in[0];
    const float* mask = (const float*)d_in[1];
    const float* ti   = (const float*)d_in[2];
    const float* wih  = (const float*)d_in[3];
    const float* whh  = (const float*)d_in[4];
    const float* bih  = (const float*)d_in[5];
    const float* bhh  = (const float*)d_in[6];
    const float* wfc  = (const float*)d_in[7];
    const float* bfc  = (const float*)d_in[8];
    float* out = (float*)d_out;

    cudaFuncSetAttribute(k_xg, cudaFuncAttributeMaxDynamicSharedMemorySize, XG_SMEM);
    cudaFuncSetAttribute(k_rec, cudaFuncAttributeMaxDynamicSharedMemorySize, R_SMEM);

    k_prep_xt<<<(NS * NB * KP2 + 255) / 256, 256>>>(x, mask, ti);
    k_prep_w<<<(NG * NH + 255) / 256, 256>>>(wih, whh, bih, bhh);
    k_xg<<<dim3(64, 512), 256, XG_SMEM>>>();
    k_rec<<<128, 256, R_SMEM>>>();
    k_fc<<<(NB * NO + 255) / 256, 256>>>(wfc, bfc, out);
}